// round 5
// baseline (speedup 1.0000x reference)
#include <cuda_runtime.h>
#include <math.h>

#define BB 16
#define NN 2048
#define MM 2048
#define TPB 256
#define RPB 64
#define PARTS (NN / RPB)      /* 32 */
#define SKIP_T (-57.5f)       /* log2 threshold: maxe*2048 << 1e-9 */

/* ---- scratch: __device__ globals (no runtime allocation) ---- */
__device__ float4 g_c4[(size_t)BB * MM];        /* per-pass folded coefficients */
__device__ float g_rowmin[BB * NN];
__device__ float g_rl[BB * NN];
__device__ float g_rlors[BB * NN];
__device__ float g_cost[BB * NN];
__device__ float g_D[BB * NN];
__device__ float g_rr[BB * MM];
__device__ float g_q[BB * MM];
__device__ float g_part[(size_t)BB * PARTS * MM];

__device__ __forceinline__ float fast_exp2(float x) {
    float r;
    asm("ex2.approx.ftz.f32 %0, %1;" : "=f"(r) : "f"(x));
    return r;
}
__device__ __forceinline__ float fast_rsqrt(float x) {
    float r;
    asm("rsqrt.approx.f32 %0, %1;" : "=f"(r) : "f"(x));
    return r;
}

__global__ void __launch_bounds__(TPB) k_init() {
    int i = blockIdx.x * TPB + threadIdx.x;
    if (i < BB * NN) { g_rl[i] = 1.0f; g_cost[i] = 0.0f; }
    if (i < BB * MM) g_rr[i] = 1.0f;  /* n==m -> factorl=factorr=1 */
}

/* Per-row min d2 (for dead-row skipping). Thread-per-row, xyz2 in smem. */
__global__ void __launch_bounds__(TPB) k_rowmin(const float* __restrict__ xyz1,
                                                const float* __restrict__ xyz2) {
    __shared__ __align__(16) float4 s2[MM];
    const int tid = threadIdx.x;
    const int b = blockIdx.y;
    for (int j = tid; j < MM; j += TPB) {
        const float* p = xyz2 + (size_t)(b * MM + j) * 3;
        float x = p[0], y = p[1], z = p[2];
        s2[j] = make_float4(x, y, z, x * x + y * y + z * z);
    }
    __syncthreads();
    int row = blockIdx.x * TPB + tid;
    int gi = b * NN + row;
    float x1 = xyz1[(size_t)gi * 3 + 0];
    float y1 = xyz1[(size_t)gi * 3 + 1];
    float z1 = xyz1[(size_t)gi * 3 + 2];
    float n1 = x1 * x1 + y1 * y1 + z1 * z1;
    float m = 3.4e38f;
#pragma unroll 4
    for (int j = 0; j < MM; j++) {
        float4 p = s2[j];
        float dot = fmaf(x1, p.x, fmaf(y1, p.y, z1 * p.z));
        float d2 = fmaf(-2.0f, dot, n1 + p.w);
        m = fminf(m, d2);
    }
    g_rowmin[gi] = m;
}

/* Per-pass folded coefficients: (xs, ys, zs, w) = (-2c*x2, -2c*y2, -2c*z2, c*|x2|^2) */
__global__ void __launch_bounds__(TPB) k_coef(float c, const float* __restrict__ xyz2) {
    int i = blockIdx.x * TPB + threadIdx.x;   /* 0 .. BB*MM */
    float x = xyz2[(size_t)i * 3 + 0];
    float y = xyz2[(size_t)i * 3 + 1];
    float z = xyz2[(size_t)i * 3 + 2];
    float m2c = -2.0f * c;
    g_c4[i] = make_float4(m2c * x, m2c * y, m2c * z, c * (x * x + y * y + z * z));
}

/* Fused round kernel: thread owns 8 columns j = tid*8 .. tid*8+7, fully
 * register-resident per-column state (coefficients, rr, q, col partials).
 * A-side (doA): e = exp2(cA*d2); rowsum; rlors = rl/(rowsum+1e-9); col partials.
 * C-side (doC): weights of the previous round = e^4; dist on the fly;
 *               cost += rlors_prev*sum(e^4*q*dist); rl -= rlors_prev*sum(e^4*q). */
__global__ void __launch_bounds__(TPB) k_round(float cA, float invC, int doC, int doA,
                                               const float* __restrict__ xyz1) {
    __shared__ float s_redbuf[48];
    const int tid = threadIdx.x;
    const int b = blockIdx.y;
    const int bx = blockIdx.x;

    const float4* C4 = g_c4 + (size_t)b * MM;
    float4 cf[8];
#pragma unroll
    for (int k = 0; k < 8; k++) cf[k] = C4[tid * 8 + k];

    float rrv[8] = {0, 0, 0, 0, 0, 0, 0, 0};
    float qv[8] = {0, 0, 0, 0, 0, 0, 0, 0};
    if (doA) {
        const float4* R = (const float4*)(g_rr + (size_t)b * MM);
        float4 a = R[tid * 2], c2 = R[tid * 2 + 1];
        rrv[0] = a.x; rrv[1] = a.y; rrv[2] = a.z; rrv[3] = a.w;
        rrv[4] = c2.x; rrv[5] = c2.y; rrv[6] = c2.z; rrv[7] = c2.w;
    }
    if (doC) {
        const float4* Q = (const float4*)(g_q + (size_t)b * MM);
        float4 a = Q[tid * 2], c2 = Q[tid * 2 + 1];
        qv[0] = a.x; qv[1] = a.y; qv[2] = a.z; qv[3] = a.w;
        qv[4] = c2.x; qv[5] = c2.y; qv[6] = c2.z; qv[7] = c2.w;
    }

    float tv[8] = {0, 0, 0, 0, 0, 0, 0, 0};
    int pr = 0;

    for (int r = 0; r < RPB; r++) {
        int row = bx * RPB + r;
        int gi = b * NN + row;
        float rlors_prev = doC ? g_rlors[gi] : 0.0f;
        bool actC = doC && (rlors_prev != 0.0f);
        bool actA = doA && (cA * g_rowmin[gi] >= SKIP_T);
        if (!actA && !actC) {
            if (doA && tid == 0) g_rlors[gi] = 0.0f;
            continue;
        }
        float x1 = xyz1[(size_t)gi * 3 + 0];
        float y1 = xyz1[(size_t)gi * 3 + 1];
        float z1 = xyz1[(size_t)gi * 3 + 2];
        float cn1 = cA * (x1 * x1 + y1 * y1 + z1 * z1);

        float ev[8];
        float racc = 0.f, cacc = 0.f, lacc = 0.f;
#pragma unroll
        for (int k = 0; k < 8; k++) {
            float t = fmaf(z1, cf[k].z, cn1 + cf[k].w);
            t = fmaf(y1, cf[k].y, t);
            t = fmaf(x1, cf[k].x, t);
            float e = fast_exp2(t);
            ev[k] = e;
            if (actA) racc = fmaf(e, rrv[k], racc);
            if (actC) {
                float d2 = fmaxf(t * invC, 1e-12f);
                float dist = d2 * fast_rsqrt(d2);
                float e2 = e * e;
                float w = (e2 * e2) * qv[k];
                cacc = fmaf(w, dist, cacc);
                lacc += w;
            }
        }
        /* block-reduce (cacc, lacc, racc) */
        float va = cacc, vb = lacc, vc = racc;
#pragma unroll
        for (int o = 16; o > 0; o >>= 1) {
            va += __shfl_xor_sync(0xffffffffu, va, o);
            vb += __shfl_xor_sync(0xffffffffu, vb, o);
            vc += __shfl_xor_sync(0xffffffffu, vc, o);
        }
        float* red = s_redbuf + (pr & 1) * 24;
        if ((tid & 31) == 0) {
            int w = tid >> 5;
            red[w] = va; red[8 + w] = vb; red[16 + w] = vc;
        }
        __syncthreads();
        float Rc = 0.f, Rl = 0.f, Rs = 0.f;
#pragma unroll
        for (int k = 0; k < 8; k++) { Rc += red[k]; Rl += red[8 + k]; Rs += red[16 + k]; }
        pr++;

        float rl = g_rl[gi];
        float rl_new = actC ? fmaxf(rl - rlors_prev * Rl, 0.0f) : rl;
        if (tid == 0 && actC) {
            g_cost[gi] += rlors_prev * Rc;
            g_rl[gi] = rl_new;
        }
        if (actA) {
            float rlors_new = rl_new / (Rs + 1e-9f);
            if (tid == 0) g_rlors[gi] = rlors_new;
#pragma unroll
            for (int k = 0; k < 8; k++) tv[k] = fmaf(ev[k], rlors_new, tv[k]);
        } else if (doA) {
            if (tid == 0) g_rlors[gi] = 0.0f;
        }
    }
    if (doA) {
        float4* P = (float4*)(g_part + ((size_t)b * PARTS + bx) * MM);
        P[tid * 2]     = make_float4(tv[0], tv[1], tv[2], tv[3]);
        P[tid * 2 + 1] = make_float4(tv[4], tv[5], tv[6], tv[7]);
    }
}

/* Column pass: t_j = sum partials; s = min(rr/(rr*t+1e-9),1); q = rr*s; rr -= q*t. */
__global__ void __launch_bounds__(TPB) k_colB() {
    int i = blockIdx.x * TPB + threadIdx.x;
    int b = i / MM, j = i - b * MM;
    const float* P = g_part + (size_t)b * PARTS * MM + j;
    float t = 0.f;
#pragma unroll 8
    for (int p = 0; p < PARTS; p++) t += P[(size_t)p * MM];
    float rr = g_rr[i];
    float ss2 = rr * t;
    float s = fminf(rr / (ss2 + 1e-9f), 1.0f);
    float q = rr * s;
    g_q[i] = q;
    g_rr[i] = fmaxf(rr - q * t, 0.0f);
}

/* Final pass: C-side of round p=0 (e = exp2(c0*d2), no pow4) fused with the
 * level-0 row sums D_i = sum_j rr_j * dist_ij. Uses c0-folded g_c4. */
__global__ void __launch_bounds__(TPB) k_final(float invC0,
                                               const float* __restrict__ xyz1) {
    __shared__ float s_redbuf[48];
    const int tid = threadIdx.x;
    const int b = blockIdx.y;
    const int bx = blockIdx.x;

    const float4* C4 = g_c4 + (size_t)b * MM;
    float4 cf[8];
#pragma unroll
    for (int k = 0; k < 8; k++) cf[k] = C4[tid * 8 + k];

    float rrv[8], qv[8];
    {
        const float4* R = (const float4*)(g_rr + (size_t)b * MM);
        const float4* Q = (const float4*)(g_q + (size_t)b * MM);
        float4 a = R[tid * 2], c2 = R[tid * 2 + 1];
        rrv[0] = a.x; rrv[1] = a.y; rrv[2] = a.z; rrv[3] = a.w;
        rrv[4] = c2.x; rrv[5] = c2.y; rrv[6] = c2.z; rrv[7] = c2.w;
        a = Q[tid * 2]; c2 = Q[tid * 2 + 1];
        qv[0] = a.x; qv[1] = a.y; qv[2] = a.z; qv[3] = a.w;
        qv[4] = c2.x; qv[5] = c2.y; qv[6] = c2.z; qv[7] = c2.w;
    }
    int pr = 0;
    const float c0 = 1.0f / invC0;

    for (int r = 0; r < RPB; r++) {
        int row = bx * RPB + r;
        int gi = b * NN + row;
        float rlors_prev = g_rlors[gi];
        bool actC = (rlors_prev != 0.0f);
        float x1 = xyz1[(size_t)gi * 3 + 0];
        float y1 = xyz1[(size_t)gi * 3 + 1];
        float z1 = xyz1[(size_t)gi * 3 + 2];
        float cn1 = c0 * (x1 * x1 + y1 * y1 + z1 * z1);

        float dacc = 0.f, cacc = 0.f, lacc = 0.f;
#pragma unroll
        for (int k = 0; k < 8; k++) {
            float t = fmaf(z1, cf[k].z, cn1 + cf[k].w);
            t = fmaf(y1, cf[k].y, t);
            t = fmaf(x1, cf[k].x, t);
            float d2 = fmaxf(t * invC0, 1e-12f);
            float dist = d2 * fast_rsqrt(d2);
            dacc = fmaf(rrv[k], dist, dacc);
            if (actC) {
                float e = fast_exp2(t);
                float w = e * qv[k];
                cacc = fmaf(w, dist, cacc);
                lacc += w;
            }
        }
        float va = cacc, vb = lacc, vc = dacc;
#pragma unroll
        for (int o = 16; o > 0; o >>= 1) {
            va += __shfl_xor_sync(0xffffffffu, va, o);
            vb += __shfl_xor_sync(0xffffffffu, vb, o);
            vc += __shfl_xor_sync(0xffffffffu, vc, o);
        }
        float* red = s_redbuf + (pr & 1) * 24;
        if ((tid & 31) == 0) {
            int w = tid >> 5;
            red[w] = va; red[8 + w] = vb; red[16 + w] = vc;
        }
        __syncthreads();
        float Rc = 0.f, Rl = 0.f, Rd = 0.f;
#pragma unroll
        for (int k = 0; k < 8; k++) { Rc += red[k]; Rl += red[8 + k]; Rd += red[16 + k]; }
        pr++;

        if (tid == 0) {
            if (actC) {
                g_cost[gi] += rlors_prev * Rc;
                g_rl[gi] = fmaxf(g_rl[gi] - rlors_prev * Rl, 0.0f);
            }
            g_D[gi] = Rd;
        }
    }
}

/* Epilogue per batch (level-0 round in closed form):
 * S = sum rr; RLOR = sum(rl)/(S+1e-9); q_j ~= rr_j*min(1/RLOR,1);
 * out = sum cost + min(1/RLOR,1) * sum(rl_i*D_i)/(S+1e-9). */
__global__ void __launch_bounds__(TPB) k_epi(float* __restrict__ out) {
    __shared__ float red[32];
    int b = blockIdx.x, tid = threadIdx.x;
    float S = 0.f, C = 0.f, L = 0.f, LD = 0.f;
    for (int j = tid; j < MM; j += TPB) S += g_rr[b * MM + j];
    for (int i = tid; i < NN; i += TPB) {
        C += g_cost[b * NN + i];
        float rl = g_rl[b * NN + i];
        L += rl;
        LD += rl * g_D[b * NN + i];
    }
#pragma unroll
    for (int o = 16; o > 0; o >>= 1) {
        S  += __shfl_xor_sync(0xffffffffu, S, o);
        C  += __shfl_xor_sync(0xffffffffu, C, o);
        L  += __shfl_xor_sync(0xffffffffu, L, o);
        LD += __shfl_xor_sync(0xffffffffu, LD, o);
    }
    if ((tid & 31) == 0) {
        int w = tid >> 5;
        red[w] = S; red[8 + w] = C; red[16 + w] = L; red[24 + w] = LD;
    }
    __syncthreads();
    if (tid == 0) {
        float Sf = 0.f, Cf = 0.f, Lf = 0.f, LDf = 0.f;
#pragma unroll
        for (int k = 0; k < 8; k++) {
            Sf += red[k]; Cf += red[8 + k]; Lf += red[16 + k]; LDf += red[24 + k];
        }
        float Sden = Sf + 1e-9f;
        float RLOR = Lf / Sden;
        float kk = fminf(1.0f / RLOR, 1.0f);
        out[b] = Cf + kk * LDf / Sden;
    }
}

extern "C" void kernel_launch(void* const* d_in, const int* in_sizes, int n_in,
                              void* d_out, int out_size) {
    const float* xyz1 = (const float*)d_in[0];
    const float* xyz2 = (const float*)d_in[1];
    float* out = (float*)d_out;

    k_init<<<(BB * NN) / TPB, TPB>>>();
    k_rowmin<<<dim3(NN / TPB, BB), TPB>>>(xyz1, xyz2);

    /* c[p] = level_p * log2(e), level_p = -0.25 * 4^p  (p = 8..0) */
    float c[9];
    for (int p = 0; p <= 8; p++)
        c[p] = (float)(-0.25 * pow(4.0, (double)p) * 1.4426950408889634);

    dim3 rg(PARTS, BB);
    /* Round p=8: A only */
    k_coef<<<(BB * MM) / TPB, TPB>>>(c[8], xyz2);
    k_round<<<rg, TPB>>>(c[8], 1.0f / c[8], 0, 1, xyz1);
    k_colB<<<(BB * MM) / TPB, TPB>>>();
    /* Fused C(p+1)+A(p) for p=7..0 */
    for (int p = 7; p >= 0; p--) {
        k_coef<<<(BB * MM) / TPB, TPB>>>(c[p], xyz2);
        k_round<<<rg, TPB>>>(c[p], 1.0f / c[p], 1, 1, xyz1);
        k_colB<<<(BB * MM) / TPB, TPB>>>();
    }
    /* C(0) fused with level-0 row sums; g_c4 still holds c[0] coefficients */
    k_final<<<rg, TPB>>>(1.0f / c[0], xyz1);
    k_epi<<<BB, TPB>>>(out);
}

// round 6
// speedup vs baseline: 1.2676x; 1.2676x over previous
#include <cuda_runtime.h>
#include <math.h>

#define BB 16
#define NN 2048
#define MM 2048
#define TPB 256
#define RPB 64
#define PARTS (NN / RPB)      /* 32 */
#define SKIP_T (-57.5f)       /* log2 threshold: rowsum << 1e-9 -> mass < 1e-5 */

/* ---- scratch: __device__ globals (no runtime allocation) ---- */
__device__ float4 g_p2[(size_t)BB * MM];   /* (x2, y2, z2, |x2|^2) */
__device__ float g_rowmin[BB * NN];
__device__ float g_rl[BB * NN];
__device__ float g_rlors[BB * NN];
__device__ float g_D[BB * NN];
__device__ float g_rr[BB * MM];
__device__ float g_q[BB * MM];
__device__ float g_part[(size_t)BB * PARTS * MM];
__device__ float g_costp[BB * PARTS];

__device__ __forceinline__ float fast_exp2(float x) {
    float r;
    asm("ex2.approx.ftz.f32 %0, %1;" : "=f"(r) : "f"(x));
    return r;
}
__device__ __forceinline__ float fast_rsqrt(float x) {
    float r;
    asm("rsqrt.approx.f32 %0, %1;" : "=f"(r) : "f"(x));
    return r;
}

__global__ void __launch_bounds__(TPB) k_init() {
    int i = blockIdx.x * TPB + threadIdx.x;
    if (i < BB * NN) g_rl[i] = 1.0f;
    if (i < BB * MM) g_rr[i] = 1.0f;       /* n==m -> factorl=factorr=1 */
    if (i < BB * PARTS) g_costp[i] = 0.0f;
}

/* Fill g_p2 + per-row min d2 (dead-row skipping). Thread-per-row. */
__global__ void __launch_bounds__(TPB) k_pre(const float* __restrict__ xyz1,
                                             const float* __restrict__ xyz2) {
    __shared__ __align__(16) float4 s2[MM];
    const int tid = threadIdx.x;
    const int b = blockIdx.y;
    for (int j = tid; j < MM; j += TPB) {
        const float* p = xyz2 + (size_t)(b * MM + j) * 3;
        float x = p[0], y = p[1], z = p[2];
        float4 v = make_float4(x, y, z, x * x + y * y + z * z);
        s2[j] = v;
        if (blockIdx.x == 0) g_p2[(size_t)b * MM + j] = v;
    }
    __syncthreads();
    int row = blockIdx.x * TPB + tid;
    int gi = b * NN + row;
    float x1 = xyz1[(size_t)gi * 3 + 0];
    float y1 = xyz1[(size_t)gi * 3 + 1];
    float z1 = xyz1[(size_t)gi * 3 + 2];
    float n1 = x1 * x1 + y1 * y1 + z1 * z1;
    float m = 3.4e38f;
#pragma unroll 4
    for (int j = 0; j < MM; j++) {
        float4 p = s2[j];
        float dot = fmaf(x1, p.x, fmaf(y1, p.y, z1 * p.z));
        float d2 = fmaf(-2.0f, dot, n1 + p.w);
        m = fminf(m, d2);
    }
    g_rowmin[gi] = m;
}

/* Fused round kernel: thread owns 8 columns (tid*8..tid*8+7); coefficients,
 * rr, q, column partials all register-resident. Row scalars prefetched to
 * smem; active rows compacted (deterministic) so skipped passes are ~free.
 * A-side: e = exp2(cA*d2); rowsum -> rlors; col partials tv += e*rlors.
 * C-side: prev round's weights e^4; dist on the fly; cost deferred per block;
 *         rl -= rlors_prev * sum(e^4*q). */
__global__ void __launch_bounds__(TPB) k_round(float cA, float invC, int doC, int doA,
                                               const float* __restrict__ xyz1) {
    __shared__ float s_x1[RPB], s_y1[RPB], s_z1[RPB], s_n1c[RPB];
    __shared__ float s_rlp[RPB], s_rl[RPB];
    __shared__ int s_mode[RPB];
    __shared__ int s_list[RPB];
    __shared__ int s_cnt;
    __shared__ float s_red[2][16];   /* [buf][lacc x8 | racc x8] */
    __shared__ float s_red1[8];
    const int tid = threadIdx.x;
    const int b = blockIdx.y;
    const int bx = blockIdx.x;

    /* coefficients from the static point table */
    const float m2c = -2.0f * cA;
    float cfx[8], cfy[8], cfz[8], cfw[8];
    {
        const float4* P2 = g_p2 + (size_t)b * MM;
#pragma unroll
        for (int k = 0; k < 8; k++) {
            float4 p = P2[tid * 8 + k];
            cfx[k] = m2c * p.x; cfy[k] = m2c * p.y; cfz[k] = m2c * p.z;
            cfw[k] = cA * p.w;
        }
    }
    float rrv[8] = {0, 0, 0, 0, 0, 0, 0, 0};
    float qv[8] = {0, 0, 0, 0, 0, 0, 0, 0};
    if (doA) {
        const float4* R = (const float4*)(g_rr + (size_t)b * MM);
        float4 a = R[tid * 2], c2 = R[tid * 2 + 1];
        rrv[0] = a.x; rrv[1] = a.y; rrv[2] = a.z; rrv[3] = a.w;
        rrv[4] = c2.x; rrv[5] = c2.y; rrv[6] = c2.z; rrv[7] = c2.w;
    }
    if (doC) {
        const float4* Q = (const float4*)(g_q + (size_t)b * MM);
        float4 a = Q[tid * 2], c2 = Q[tid * 2 + 1];
        qv[0] = a.x; qv[1] = a.y; qv[2] = a.z; qv[3] = a.w;
        qv[4] = c2.x; qv[5] = c2.y; qv[6] = c2.z; qv[7] = c2.w;
    }

    /* prefetch row scalars + classify */
    if (tid < RPB) {
        int gi = b * NN + bx * RPB + tid;
        float x1 = xyz1[(size_t)gi * 3 + 0];
        float y1 = xyz1[(size_t)gi * 3 + 1];
        float z1 = xyz1[(size_t)gi * 3 + 2];
        s_x1[tid] = x1; s_y1[tid] = y1; s_z1[tid] = z1;
        s_n1c[tid] = cA * (x1 * x1 + y1 * y1 + z1 * z1);
        float rlp = doC ? g_rlors[gi] : 0.0f;
        s_rlp[tid] = rlp;
        s_rl[tid] = g_rl[gi];
        int mode = 0;
        if (doA && (cA * g_rowmin[gi] >= SKIP_T)) mode |= 1;
        if (rlp != 0.0f) mode |= 2;
        s_mode[tid] = mode;
        if (doA && !(mode & 1)) g_rlors[gi] = 0.0f;
    }
    __syncthreads();
    if (tid == 0) {
        int cnt = 0;
        for (int r = 0; r < RPB; r++)
            if (s_mode[r]) s_list[cnt++] = r | (s_mode[r] << 16);
        s_cnt = cnt;
    }
    __syncthreads();
    const int cnt = s_cnt;

    float tv[8] = {0, 0, 0, 0, 0, 0, 0, 0};
    float caccT = 0.f;

    for (int i = 0; i < cnt; i++) {
        int ent = s_list[i];
        int r = ent & 0xffff;
        bool actA = (ent >> 16) & 1;
        bool actC = (ent >> 16) & 2;
        float x1 = s_x1[r], y1 = s_y1[r], z1 = s_z1[r], n1c = s_n1c[r];
        float rlp = s_rlp[r], rl = s_rl[r];

        float ev[8];
        float racc = 0.f, cacc = 0.f, lacc = 0.f;
#pragma unroll
        for (int k = 0; k < 8; k++) {
            float t = fmaf(x1, cfx[k], fmaf(y1, cfy[k], fmaf(z1, cfz[k], n1c + cfw[k])));
            float e = fast_exp2(t);
            ev[k] = e;
            if (actA) racc = fmaf(e, rrv[k], racc);
            if (actC) {
                float d2 = fmaxf(t * invC, 1e-12f);
                float dist = d2 * fast_rsqrt(d2);
                float e2 = e * e;
                float w = (e2 * e2) * qv[k];
                cacc = fmaf(w, dist, cacc);
                lacc += w;
            }
        }
        /* reduce (lacc, racc) block-wide; cacc deferred per-thread */
        float va = lacc, vb = racc;
#pragma unroll
        for (int o = 16; o > 0; o >>= 1) {
            va += __shfl_xor_sync(0xffffffffu, va, o);
            vb += __shfl_xor_sync(0xffffffffu, vb, o);
        }
        float* red = s_red[i & 1];
        if ((tid & 31) == 0) {
            int w = tid >> 5;
            red[w] = va; red[8 + w] = vb;
        }
        __syncthreads();
        float Rl = 0.f, Rs = 0.f;
#pragma unroll
        for (int k = 0; k < 8; k++) { Rl += red[k]; Rs += red[8 + k]; }

        caccT = fmaf(rlp, cacc, caccT);
        float rl_new = actC ? fmaxf(rl - rlp * Rl, 0.0f) : rl;
        int gi = b * NN + bx * RPB + r;
        if (tid == 0 && actC) g_rl[gi] = rl_new;
        if (actA) {
            float rlors_new = rl_new / (Rs + 1e-9f);
            if (tid == 0) g_rlors[gi] = rlors_new;
#pragma unroll
            for (int k = 0; k < 8; k++) tv[k] = fmaf(ev[k], rlors_new, tv[k]);
        }
    }

    if (doA) {
        float4* P = (float4*)(g_part + ((size_t)b * PARTS + bx) * MM);
        P[tid * 2]     = make_float4(tv[0], tv[1], tv[2], tv[3]);
        P[tid * 2 + 1] = make_float4(tv[4], tv[5], tv[6], tv[7]);
    }
    if (doC) {
        float v = caccT;
#pragma unroll
        for (int o = 16; o > 0; o >>= 1) v += __shfl_xor_sync(0xffffffffu, v, o);
        if ((tid & 31) == 0) s_red1[tid >> 5] = v;
        __syncthreads();
        if (tid == 0) {
            float s = 0.f;
#pragma unroll
            for (int k = 0; k < 8; k++) s += s_red1[k];
            g_costp[b * PARTS + bx] += s;
        }
    }
}

/* Column pass: t_j = sum partials; s = min(rr/(rr*t+1e-9),1); q = rr*s; rr -= q*t. */
__global__ void __launch_bounds__(TPB) k_colB() {
    int i = blockIdx.x * TPB + threadIdx.x;
    int b = i / MM, j = i - b * MM;
    const float* P = g_part + (size_t)b * PARTS * MM + j;
    float t = 0.f;
#pragma unroll 8
    for (int p = 0; p < PARTS; p++) t += P[(size_t)p * MM];
    float rr = g_rr[i];
    float ss2 = rr * t;
    float s = fminf(rr / (ss2 + 1e-9f), 1.0f);
    float q = rr * s;
    g_q[i] = q;
    g_rr[i] = fmaxf(rr - q * t, 0.0f);
}

/* Final pass: C-side of round p=0 fused with level-0 row sums
 * D_i = sum_j rr_j * dist_ij. All rows active (D needed everywhere). */
__global__ void __launch_bounds__(TPB) k_final(float c0, float invC0,
                                               const float* __restrict__ xyz1) {
    __shared__ float s_x1[RPB], s_y1[RPB], s_z1[RPB], s_n1c[RPB];
    __shared__ float s_rlp[RPB], s_rl[RPB];
    __shared__ float s_red[2][16];
    __shared__ float s_red1[8];
    const int tid = threadIdx.x;
    const int b = blockIdx.y;
    const int bx = blockIdx.x;

    const float m2c = -2.0f * c0;
    float cfx[8], cfy[8], cfz[8], cfw[8];
    {
        const float4* P2 = g_p2 + (size_t)b * MM;
#pragma unroll
        for (int k = 0; k < 8; k++) {
            float4 p = P2[tid * 8 + k];
            cfx[k] = m2c * p.x; cfy[k] = m2c * p.y; cfz[k] = m2c * p.z;
            cfw[k] = c0 * p.w;
        }
    }
    float rrv[8], qv[8];
    {
        const float4* R = (const float4*)(g_rr + (size_t)b * MM);
        const float4* Q = (const float4*)(g_q + (size_t)b * MM);
        float4 a = R[tid * 2], c2 = R[tid * 2 + 1];
        rrv[0] = a.x; rrv[1] = a.y; rrv[2] = a.z; rrv[3] = a.w;
        rrv[4] = c2.x; rrv[5] = c2.y; rrv[6] = c2.z; rrv[7] = c2.w;
        a = Q[tid * 2]; c2 = Q[tid * 2 + 1];
        qv[0] = a.x; qv[1] = a.y; qv[2] = a.z; qv[3] = a.w;
        qv[4] = c2.x; qv[5] = c2.y; qv[6] = c2.z; qv[7] = c2.w;
    }
    if (tid < RPB) {
        int gi = b * NN + bx * RPB + tid;
        float x1 = xyz1[(size_t)gi * 3 + 0];
        float y1 = xyz1[(size_t)gi * 3 + 1];
        float z1 = xyz1[(size_t)gi * 3 + 2];
        s_x1[tid] = x1; s_y1[tid] = y1; s_z1[tid] = z1;
        s_n1c[tid] = c0 * (x1 * x1 + y1 * y1 + z1 * z1);
        s_rlp[tid] = g_rlors[gi];
        s_rl[tid] = g_rl[gi];
    }
    __syncthreads();

    float caccT = 0.f;
    for (int r = 0; r < RPB; r++) {
        float x1 = s_x1[r], y1 = s_y1[r], z1 = s_z1[r], n1c = s_n1c[r];
        float rlp = s_rlp[r], rl = s_rl[r];
        bool actC = (rlp != 0.0f);

        float dacc = 0.f, cacc = 0.f, lacc = 0.f;
#pragma unroll
        for (int k = 0; k < 8; k++) {
            float t = fmaf(x1, cfx[k], fmaf(y1, cfy[k], fmaf(z1, cfz[k], n1c + cfw[k])));
            float d2 = fmaxf(t * invC0, 1e-12f);
            float dist = d2 * fast_rsqrt(d2);
            dacc = fmaf(rrv[k], dist, dacc);
            if (actC) {
                float e = fast_exp2(t);
                float w = e * qv[k];
                cacc = fmaf(w, dist, cacc);
                lacc += w;
            }
        }
        float va = lacc, vb = dacc;
#pragma unroll
        for (int o = 16; o > 0; o >>= 1) {
            va += __shfl_xor_sync(0xffffffffu, va, o);
            vb += __shfl_xor_sync(0xffffffffu, vb, o);
        }
        float* red = s_red[r & 1];
        if ((tid & 31) == 0) {
            int w = tid >> 5;
            red[w] = va; red[8 + w] = vb;
        }
        __syncthreads();
        float Rl = 0.f, Rd = 0.f;
#pragma unroll
        for (int k = 0; k < 8; k++) { Rl += red[k]; Rd += red[8 + k]; }

        caccT = fmaf(rlp, cacc, caccT);
        if (tid == 0) {
            int gi = b * NN + bx * RPB + r;
            if (actC) g_rl[gi] = fmaxf(rl - rlp * Rl, 0.0f);
            g_D[gi] = Rd;
        }
    }
    {
        float v = caccT;
#pragma unroll
        for (int o = 16; o > 0; o >>= 1) v += __shfl_xor_sync(0xffffffffu, v, o);
        if ((tid & 31) == 0) s_red1[tid >> 5] = v;
        __syncthreads();
        if (tid == 0) {
            float s = 0.f;
#pragma unroll
            for (int k = 0; k < 8; k++) s += s_red1[k];
            g_costp[b * PARTS + bx] += s;
        }
    }
}

/* Epilogue per batch (level-0 round closed form):
 * S = sum rr; RLOR = sum(rl)/(S+1e-9); q_j ~= rr_j*min(1/RLOR,1);
 * out = sum cost + min(1/RLOR,1) * sum(rl_i*D_i)/(S+1e-9). */
__global__ void __launch_bounds__(TPB) k_epi(float* __restrict__ out) {
    __shared__ float red[32];
    int b = blockIdx.x, tid = threadIdx.x;
    float S = 0.f, C = 0.f, L = 0.f, LD = 0.f;
    for (int j = tid; j < MM; j += TPB) S += g_rr[b * MM + j];
    if (tid < PARTS) C = g_costp[b * PARTS + tid];
    for (int i = tid; i < NN; i += TPB) {
        float rl = g_rl[b * NN + i];
        L += rl;
        LD += rl * g_D[b * NN + i];
    }
#pragma unroll
    for (int o = 16; o > 0; o >>= 1) {
        S  += __shfl_xor_sync(0xffffffffu, S, o);
        C  += __shfl_xor_sync(0xffffffffu, C, o);
        L  += __shfl_xor_sync(0xffffffffu, L, o);
        LD += __shfl_xor_sync(0xffffffffu, LD, o);
    }
    if ((tid & 31) == 0) {
        int w = tid >> 5;
        red[w] = S; red[8 + w] = C; red[16 + w] = L; red[24 + w] = LD;
    }
    __syncthreads();
    if (tid == 0) {
        float Sf = 0.f, Cf = 0.f, Lf = 0.f, LDf = 0.f;
#pragma unroll
        for (int k = 0; k < 8; k++) {
            Sf += red[k]; Cf += red[8 + k]; Lf += red[16 + k]; LDf += red[24 + k];
        }
        float Sden = Sf + 1e-9f;
        float RLOR = Lf / Sden;
        float kk = fminf(1.0f / RLOR, 1.0f);
        out[b] = Cf + kk * LDf / Sden;
    }
}

extern "C" void kernel_launch(void* const* d_in, const int* in_sizes, int n_in,
                              void* d_out, int out_size) {
    const float* xyz1 = (const float*)d_in[0];
    const float* xyz2 = (const float*)d_in[1];
    float* out = (float*)d_out;

    k_init<<<(BB * NN) / TPB, TPB>>>();
    k_pre<<<dim3(NN / TPB, BB), TPB>>>(xyz1, xyz2);

    /* c[p] = level_p * log2(e), level_p = -0.25 * 4^p  (p = 8..0) */
    float c[9];
    for (int p = 0; p <= 8; p++)
        c[p] = (float)(-0.25 * pow(4.0, (double)p) * 1.4426950408889634);

    dim3 rg(PARTS, BB);
    k_round<<<rg, TPB>>>(c[8], 1.0f / c[8], 0, 1, xyz1);
    k_colB<<<(BB * MM) / TPB, TPB>>>();
    for (int p = 7; p >= 0; p--) {
        k_round<<<rg, TPB>>>(c[p], 1.0f / c[p], 1, 1, xyz1);
        k_colB<<<(BB * MM) / TPB, TPB>>>();
    }
    k_final<<<rg, TPB>>>(c[0], 1.0f / c[0], xyz1);
    k_epi<<<BB, TPB>>>(out);
}

// round 8
// speedup vs baseline: 1.4960x; 1.1802x over previous
#include <cuda_runtime.h>
#include <math.h>

#define BB 16
#define NN 2048
#define MM 2048
#define TPB 256
#define RPB 64
#define PARTS (NN / RPB)      /* 32 */
#define SKIP_T (-57.5f)       /* log2 threshold: rowsum << 1e-9 -> mass < 1e-5 */

/* ---- scratch: __device__ globals (no runtime allocation) ---- */
__device__ float4 g_p2[(size_t)BB * MM];   /* (x2, y2, z2, |x2|^2) */
__device__ float g_rowmin[BB * NN];
__device__ float g_rl[BB * NN];
__device__ float g_rlors[BB * NN];
__device__ float g_D[BB * NN];
__device__ float g_rr[BB * MM];
__device__ float g_q[BB * MM];
__device__ float g_part[(size_t)BB * PARTS * MM];
__device__ float g_costp[BB * PARTS];

__device__ __forceinline__ float fast_exp2(float x) {
    float r;
    asm("ex2.approx.ftz.f32 %0, %1;" : "=f"(r) : "f"(x));
    return r;
}
__device__ __forceinline__ float fast_rsqrt(float x) {
    float r;
    asm("rsqrt.approx.f32 %0, %1;" : "=f"(r) : "f"(x));
    return r;
}
__device__ __forceinline__ float warp_sum(float v) {
#pragma unroll
    for (int o = 16; o > 0; o >>= 1) v += __shfl_xor_sync(0xffffffffu, v, o);
    return v;
}

__global__ void __launch_bounds__(TPB) k_init() {
    int i = blockIdx.x * TPB + threadIdx.x;
    if (i < BB * NN) g_rl[i] = 1.0f;
    if (i < BB * MM) g_rr[i] = 1.0f;       /* n==m -> factorl=factorr=1 */
    if (i < BB * PARTS) g_costp[i] = 0.0f;
}

/* Fill g_p2 + per-row min d2 (dead-row skipping). Thread-per-row. */
__global__ void __launch_bounds__(TPB) k_pre(const float* __restrict__ xyz1,
                                             const float* __restrict__ xyz2) {
    __shared__ __align__(16) float4 s2[MM];
    const int tid = threadIdx.x;
    const int b = blockIdx.y;
    for (int j = tid; j < MM; j += TPB) {
        const float* p = xyz2 + (size_t)(b * MM + j) * 3;
        float x = p[0], y = p[1], z = p[2];
        float4 v = make_float4(x, y, z, x * x + y * y + z * z);
        s2[j] = v;
        if (blockIdx.x == 0) g_p2[(size_t)b * MM + j] = v;
    }
    __syncthreads();
    int row = blockIdx.x * TPB + tid;
    int gi = b * NN + row;
    float x1 = xyz1[(size_t)gi * 3 + 0];
    float y1 = xyz1[(size_t)gi * 3 + 1];
    float z1 = xyz1[(size_t)gi * 3 + 2];
    float n1 = x1 * x1 + y1 * y1 + z1 * z1;
    float m = 3.4e38f;
#pragma unroll 4
    for (int j = 0; j < MM; j++) {
        float4 p = s2[j];
        float dot = fmaf(x1, p.x, fmaf(y1, p.y, z1 * p.z));
        float d2 = fmaf(-2.0f, dot, n1 + p.w);
        m = fminf(m, d2);
    }
    g_rowmin[gi] = m;
}

/* Fused round kernel, 3-phase / 2-barrier structure.
 * Thread owns 8 columns (tid*8..tid*8+7); coefficients, rr, q, column
 * partials register-resident.
 * Phase 1: per row, e = exp2(cA*d2); racc = sum e*rr (A); C-side weights
 *          e^4*q -> lacc, cost partial (deferred per-thread); per-warp
 *          partials of (racc, lacc) to smem. No barriers between rows.
 * Phase 2: threads 0..RPB-1 finalize Rs, Rl per row -> rl_new, rlors_new.
 * Phase 3: rows with rlors != 0: recompute e (bit-identical chain) and
 *          accumulate tv += e*rlors. */
__global__ void __launch_bounds__(TPB) k_round(float cA, float invC, int doC, int doA,
                                               const float* __restrict__ xyz1) {
    __shared__ float s_x1[RPB], s_y1[RPB], s_z1[RPB], s_n1c[RPB];
    __shared__ float s_rlp[RPB], s_rl[RPB];
    __shared__ float s_rlors[RPB];
    __shared__ int s_mode[RPB];
    __shared__ float s_p[RPB][16];    /* [row][racc x8 | lacc x8] per warp */
    __shared__ float s_red1[8];
    const int tid = threadIdx.x;
    const int wid = tid >> 5;
    const int b = blockIdx.y;
    const int bx = blockIdx.x;

    /* coefficients from the static point table */
    const float m2c = -2.0f * cA;
    float cfx[8], cfy[8], cfz[8], cfw[8];
    {
        const float4* P2 = g_p2 + (size_t)b * MM;
#pragma unroll
        for (int k = 0; k < 8; k++) {
            float4 p = P2[tid * 8 + k];
            cfx[k] = m2c * p.x; cfy[k] = m2c * p.y; cfz[k] = m2c * p.z;
            cfw[k] = cA * p.w;
        }
    }
    float rrv[8] = {0, 0, 0, 0, 0, 0, 0, 0};
    float qv[8] = {0, 0, 0, 0, 0, 0, 0, 0};
    if (doA) {
        const float4* R = (const float4*)(g_rr + (size_t)b * MM);
        float4 a = R[tid * 2], c2 = R[tid * 2 + 1];
        rrv[0] = a.x; rrv[1] = a.y; rrv[2] = a.z; rrv[3] = a.w;
        rrv[4] = c2.x; rrv[5] = c2.y; rrv[6] = c2.z; rrv[7] = c2.w;
    }
    if (doC) {
        const float4* Q = (const float4*)(g_q + (size_t)b * MM);
        float4 a = Q[tid * 2], c2 = Q[tid * 2 + 1];
        qv[0] = a.x; qv[1] = a.y; qv[2] = a.z; qv[3] = a.w;
        qv[4] = c2.x; qv[5] = c2.y; qv[6] = c2.z; qv[7] = c2.w;
    }

    /* prefetch row scalars + classify */
    if (tid < RPB) {
        int gi = b * NN + bx * RPB + tid;
        float x1 = xyz1[(size_t)gi * 3 + 0];
        float y1 = xyz1[(size_t)gi * 3 + 1];
        float z1 = xyz1[(size_t)gi * 3 + 2];
        s_x1[tid] = x1; s_y1[tid] = y1; s_z1[tid] = z1;
        s_n1c[tid] = cA * (x1 * x1 + y1 * y1 + z1 * z1);
        float rlp = doC ? g_rlors[gi] : 0.0f;
        s_rlp[tid] = rlp;
        s_rl[tid] = g_rl[gi];
        int mode = 0;
        if (doA && (cA * g_rowmin[gi] >= SKIP_T)) mode |= 1;
        if (rlp != 0.0f) mode |= 2;
        s_mode[tid] = mode;
        if (doA && !(mode & 1)) g_rlors[gi] = 0.0f;
    }
    __syncthreads();

    /* ---- Phase 1 ---- */
    float caccT = 0.f;
    for (int r = 0; r < RPB; r++) {
        int mode = s_mode[r];
        if (!mode) continue;
        bool actA = mode & 1;
        bool actC = mode & 2;
        float x1 = s_x1[r], y1 = s_y1[r], z1 = s_z1[r], n1c = s_n1c[r];

        float racc = 0.f, cacc = 0.f, lacc = 0.f;
#pragma unroll
        for (int k = 0; k < 8; k++) {
            float t = fmaf(x1, cfx[k], fmaf(y1, cfy[k], fmaf(z1, cfz[k], n1c + cfw[k])));
            float e = fast_exp2(t);
            if (actA) racc = fmaf(e, rrv[k], racc);
            if (actC) {
                float d2 = fmaxf(t * invC, 1e-12f);
                float dist = d2 * fast_rsqrt(d2);
                float e2 = e * e;
                float w = (e2 * e2) * qv[k];
                cacc = fmaf(w, dist, cacc);
                lacc += w;
            }
        }
        caccT = fmaf(s_rlp[r], cacc, caccT);
        float ra = warp_sum(racc);
        float la = warp_sum(lacc);
        if ((tid & 31) == 0) {
            s_p[r][wid] = ra;
            s_p[r][8 + wid] = la;
        }
    }
    __syncthreads();

    /* ---- Phase 2 ---- */
    if (tid < RPB) {
        int r = tid;
        int mode = s_mode[r];
        float rlors_new = 0.0f;
        if (mode) {
            float Rs = 0.f, Rl = 0.f;
#pragma unroll
            for (int k = 0; k < 8; k++) { Rs += s_p[r][k]; Rl += s_p[r][8 + k]; }
            int gi = b * NN + bx * RPB + r;
            float rl = s_rl[r];
            float rl_new = (mode & 2) ? fmaxf(rl - s_rlp[r] * Rl, 0.0f) : rl;
            if (mode & 2) g_rl[gi] = rl_new;
            if (mode & 1) {
                rlors_new = rl_new / (Rs + 1e-9f);
                g_rlors[gi] = rlors_new;
            }
        }
        s_rlors[r] = rlors_new;
    }
    __syncthreads();

    /* ---- Phase 3 ---- */
    if (doA) {
        float tv[8] = {0, 0, 0, 0, 0, 0, 0, 0};
        for (int r = 0; r < RPB; r++) {
            float rlors = s_rlors[r];
            if (rlors == 0.0f) continue;
            float x1 = s_x1[r], y1 = s_y1[r], z1 = s_z1[r], n1c = s_n1c[r];
#pragma unroll
            for (int k = 0; k < 8; k++) {
                float t = fmaf(x1, cfx[k], fmaf(y1, cfy[k], fmaf(z1, cfz[k], n1c + cfw[k])));
                float e = fast_exp2(t);
                tv[k] = fmaf(e, rlors, tv[k]);
            }
        }
        float4* P = (float4*)(g_part + ((size_t)b * PARTS + bx) * MM);
        P[tid * 2]     = make_float4(tv[0], tv[1], tv[2], tv[3]);
        P[tid * 2 + 1] = make_float4(tv[4], tv[5], tv[6], tv[7]);
    }
    if (doC) {
        float v = warp_sum(caccT);
        if ((tid & 31) == 0) s_red1[wid] = v;
        __syncthreads();
        if (tid == 0) {
            float s = 0.f;
#pragma unroll
            for (int k = 0; k < 8; k++) s += s_red1[k];
            g_costp[b * PARTS + bx] += s;
        }
    }
}

/* Column pass: t_j = sum partials; s = min(rr/(rr*t+1e-9),1); q = rr*s; rr -= q*t. */
__global__ void __launch_bounds__(TPB) k_colB() {
    int i = blockIdx.x * TPB + threadIdx.x;
    int b = i / MM, j = i - b * MM;
    const float* P = g_part + (size_t)b * PARTS * MM + j;
    float t = 0.f;
#pragma unroll 8
    for (int p = 0; p < PARTS; p++) t += P[(size_t)p * MM];
    float rr = g_rr[i];
    float ss2 = rr * t;
    float s = fminf(rr / (ss2 + 1e-9f), 1.0f);
    float q = rr * s;
    g_q[i] = q;
    g_rr[i] = fmaxf(rr - q * t, 0.0f);
}

/* Final pass: C-side of round p=0 fused with level-0 row sums
 * D_i = sum_j rr_j * dist_ij. Two-phase structure (no tv). */
__global__ void __launch_bounds__(TPB) k_final(float c0, float invC0,
                                               const float* __restrict__ xyz1) {
    __shared__ float s_x1[RPB], s_y1[RPB], s_z1[RPB], s_n1c[RPB];
    __shared__ float s_rlp[RPB], s_rl[RPB];
    __shared__ float s_p[RPB][16];   /* [row][lacc x8 | dacc x8] */
    __shared__ float s_red1[8];
    const int tid = threadIdx.x;
    const int wid = tid >> 5;
    const int b = blockIdx.y;
    const int bx = blockIdx.x;

    const float m2c = -2.0f * c0;
    float cfx[8], cfy[8], cfz[8], cfw[8];
    {
        const float4* P2 = g_p2 + (size_t)b * MM;
#pragma unroll
        for (int k = 0; k < 8; k++) {
            float4 p = P2[tid * 8 + k];
            cfx[k] = m2c * p.x; cfy[k] = m2c * p.y; cfz[k] = m2c * p.z;
            cfw[k] = c0 * p.w;
        }
    }
    float rrv[8], qv[8];
    {
        const float4* R = (const float4*)(g_rr + (size_t)b * MM);
        const float4* Q = (const float4*)(g_q + (size_t)b * MM);
        float4 a = R[tid * 2], c2 = R[tid * 2 + 1];
        rrv[0] = a.x; rrv[1] = a.y; rrv[2] = a.z; rrv[3] = a.w;
        rrv[4] = c2.x; rrv[5] = c2.y; rrv[6] = c2.z; rrv[7] = c2.w;
        a = Q[tid * 2]; c2 = Q[tid * 2 + 1];
        qv[0] = a.x; qv[1] = a.y; qv[2] = a.z; qv[3] = a.w;
        qv[4] = c2.x; qv[5] = c2.y; qv[6] = c2.z; qv[7] = c2.w;
    }
    if (tid < RPB) {
        int gi = b * NN + bx * RPB + tid;
        float x1 = xyz1[(size_t)gi * 3 + 0];
        float y1 = xyz1[(size_t)gi * 3 + 1];
        float z1 = xyz1[(size_t)gi * 3 + 2];
        s_x1[tid] = x1; s_y1[tid] = y1; s_z1[tid] = z1;
        s_n1c[tid] = c0 * (x1 * x1 + y1 * y1 + z1 * z1);
        s_rlp[tid] = g_rlors[gi];
        s_rl[tid] = g_rl[gi];
    }
    __syncthreads();

    float caccT = 0.f;
    for (int r = 0; r < RPB; r++) {
        float x1 = s_x1[r], y1 = s_y1[r], z1 = s_z1[r], n1c = s_n1c[r];
        float rlp = s_rlp[r];
        bool actC = (rlp != 0.0f);

        float dacc = 0.f, cacc = 0.f, lacc = 0.f;
#pragma unroll
        for (int k = 0; k < 8; k++) {
            float t = fmaf(x1, cfx[k], fmaf(y1, cfy[k], fmaf(z1, cfz[k], n1c + cfw[k])));
            float d2 = fmaxf(t * invC0, 1e-12f);
            float dist = d2 * fast_rsqrt(d2);
            dacc = fmaf(rrv[k], dist, dacc);
            if (actC) {
                float e = fast_exp2(t);
                float w = e * qv[k];
                cacc = fmaf(w, dist, cacc);
                lacc += w;
            }
        }
        caccT = fmaf(rlp, cacc, caccT);
        float la = warp_sum(lacc);
        float da = warp_sum(dacc);
        if ((tid & 31) == 0) {
            s_p[r][wid] = la;
            s_p[r][8 + wid] = da;
        }
    }
    __syncthreads();

    if (tid < RPB) {
        int r = tid;
        float Rl = 0.f, Rd = 0.f;
#pragma unroll
        for (int k = 0; k < 8; k++) { Rl += s_p[r][k]; Rd += s_p[r][8 + k]; }
        int gi = b * NN + bx * RPB + r;
        float rlp = s_rlp[r];
        if (rlp != 0.0f) g_rl[gi] = fmaxf(s_rl[r] - rlp * Rl, 0.0f);
        g_D[gi] = Rd;
    }
    {
        float v = warp_sum(caccT);
        if ((tid & 31) == 0) s_red1[wid] = v;
        __syncthreads();
        if (tid == 0) {
            float s = 0.f;
#pragma unroll
            for (int k = 0; k < 8; k++) s += s_red1[k];
            g_costp[b * PARTS + bx] += s;
        }
    }
}

/* Epilogue per batch (level-0 round closed form):
 * S = sum rr; RLOR = sum(rl)/(S+1e-9); q_j ~= rr_j*min(1/RLOR,1);
 * out = sum cost + min(1/RLOR,1) * sum(rl_i*D_i)/(S+1e-9). */
__global__ void __launch_bounds__(TPB) k_epi(float* __restrict__ out) {
    __shared__ float red[32];
    int b = blockIdx.x, tid = threadIdx.x;
    float S = 0.f, C = 0.f, L = 0.f, LD = 0.f;
    for (int j = tid; j < MM; j += TPB) S += g_rr[b * MM + j];
    if (tid < PARTS) C = g_costp[b * PARTS + tid];
    for (int i = tid; i < NN; i += TPB) {
        float rl = g_rl[b * NN + i];
        L += rl;
        LD += rl * g_D[b * NN + i];
    }
#pragma unroll
    for (int o = 16; o > 0; o >>= 1) {
        S  += __shfl_xor_sync(0xffffffffu, S, o);
        C  += __shfl_xor_sync(0xffffffffu, C, o);
        L  += __shfl_xor_sync(0xffffffffu, L, o);
        LD += __shfl_xor_sync(0xffffffffu, LD, o);
    }
    if ((tid & 31) == 0) {
        int w = tid >> 5;
        red[w] = S; red[8 + w] = C; red[16 + w] = L; red[24 + w] = LD;
    }
    __syncthreads();
    if (tid == 0) {
        float Sf = 0.f, Cf = 0.f, Lf = 0.f, LDf = 0.f;
#pragma unroll
        for (int k = 0; k < 8; k++) {
            Sf += red[k]; Cf += red[8 + k]; Lf += red[16 + k]; LDf += red[24 + k];
        }
        float Sden = Sf + 1e-9f;
        float RLOR = Lf / Sden;
        float kk = fminf(1.0f / RLOR, 1.0f);
        out[b] = Cf + kk * LDf / Sden;
    }
}

extern "C" void kernel_launch(void* const* d_in, const int* in_sizes, int n_in,
                              void* d_out, int out_size) {
    const float* xyz1 = (const float*)d_in[0];
    const float* xyz2 = (const float*)d_in[1];
    float* out = (float*)d_out;

    k_init<<<(BB * NN) / TPB, TPB>>>();
    k_pre<<<dim3(NN / TPB, BB), TPB>>>(xyz1, xyz2);

    /* c[p] = level_p * log2(e), level_p = -0.25 * 4^p  (p = 8..0) */
    float c[9];
    for (int p = 0; p <= 8; p++)
        c[p] = (float)(-0.25 * pow(4.0, (double)p) * 1.4426950408889634);

    dim3 rg(PARTS, BB);
    k_round<<<rg, TPB>>>(c[8], 1.0f / c[8], 0, 1, xyz1);
    k_colB<<<(BB * MM) / TPB, TPB>>>();
    for (int p = 7; p >= 0; p--) {
        k_round<<<rg, TPB>>>(c[p], 1.0f / c[p], 1, 1, xyz1);
        k_colB<<<(BB * MM) / TPB, TPB>>>();
    }
    k_final<<<rg, TPB>>>(c[0], 1.0f / c[0], xyz1);
    k_epi<<<BB, TPB>>>(out);
}